// round 8
// baseline (speedup 1.0000x reference)
#include <cuda_runtime.h>
#include <cuda_fp16.h>

#define D 64
#define MAXN 100000
#define MAXE 1250000
#define BN_EPS 1e-5f
#define TILE 128
#define NTHREADS 256

typedef unsigned long long ull;

#define PK2(d, s)  asm("mov.b64 %0, {%1, %1};" : "=l"(d) : "f"(s))
#define FMA2(d, a, b, c) asm("fma.rn.f32x2 %0, %1, %2, %3;" : "=l"(d) : "l"(a), "l"(b), "l"(c))
#define UPK2(lo, hi, s) asm("mov.b64 {%0, %1}, %2;" : "=f"(lo), "=f"(hi) : "l"(s))

__device__ __forceinline__ __half2 u2h2(unsigned u) { return *reinterpret_cast<__half2*>(&u); }
__device__ __forceinline__ unsigned h2u(__half2 h) { return *reinterpret_cast<unsigned*>(&h); }

// ---------------- static device scratch -------------------------------------
__device__ int   g_deg[MAXN];
__device__ int   g_rowptr[MAXN + 1];
__device__ int   g_cursor[MAXN + 1];
__device__ int   g_blocksums[256];
__device__ int   g_srcsorted[MAXE];
__device__ __align__(16) __half g_xh[(size_t)MAXN * D];
__device__ __align__(16) float  g_msg[(size_t)MAXN * D];
__device__ __align__(16) __half g_hA[(size_t)MAXN * D];
__device__ __align__(16) __half g_hB[(size_t)MAXN * D];
__device__ __align__(16) float g_s0[D];
__device__ __align__(16) float g_q0[D];
__device__ __align__(16) float g_s1[D];
__device__ __align__(16) float g_q1[D];
__device__ unsigned g_bar_cnt;   // monotonic, never reset

// ---------------- grid barrier (monotonic counter, wrap-safe) ----------------
__device__ __forceinline__ void grid_bar() {
    __syncthreads();
    if (threadIdx.x == 0) {
        __threadfence();
        unsigned t = atomicAdd(&g_bar_cnt, 1u);
        unsigned target = t - (t % gridDim.x) + gridDim.x;
        if ((t % gridDim.x) != gridDim.x - 1) {
            volatile unsigned* p = &g_bar_cnt;
            while ((int)(*p - target) < 0) __nanosleep(64);
        }
        __threadfence();
    }
    __syncthreads();
}

// ---------------- smem layout -------------------------------------------------
#define WROW 68
#define AROW 68
#define OFF_WB  (64 * WROW)
#define OFF_M   (2 * 64 * WROW)
#define OFF_X   (OFF_M + TILE * AROW)
#define OFF_BR  (OFF_X + TILE * AROW)
#define OFF_SC  (OFF_BR + 64)
#define OFF_SH  (OFF_SC + 64)
#define OFF_SUM (OFF_SH + 64)
#define OFF_SQ  (OFF_SUM + 64)
#define SMEM_FLOATS (OFF_SQ + 64)

// ---------------- gather phase ------------------------------------------------
template<int TF>
__device__ void gather_phase(const __half* __restrict__ x_src,
                             const float* __restrict__ ssum, const float* __restrict__ ssq,
                             const float* __restrict__ gamma_p, const float* __restrict__ beta_p,
                             float invN, int N)
{
    int lane = threadIdx.x & 31;
    int gw = (blockIdx.x * NTHREADS + threadIdx.x) >> 5;
    int nw = gridDim.x * (NTHREADS / 32);
    int chunk = (N + nw - 1) / nw;
    int n0 = gw * chunk;
    int n1 = min(N, n0 + chunk);
    if (n0 >= n1) return;
    int q = lane >> 3;
    int c8 = lane & 7;

    __half2 sc2[4], sh2[4];
    if (TF) {
#pragma unroll
        for (int j = 0; j < 4; j++) {
            float scf[2], shf[2];
#pragma unroll
            for (int c = 0; c < 2; c++) {
                int col = c8 * 8 + j * 2 + c;
                float mean = ssum[col] * invN;
                float var = fmaf(-mean, mean, ssq[col] * invN);
                var = var < 0.f ? 0.f : var;
                float s = gamma_p[col] * rsqrtf(var + BN_EPS);
                scf[c] = s;
                shf[c] = beta_p[col] - mean * s;
            }
            sc2[j] = __floats2half2_rn(scf[0], scf[1]);
            sh2[j] = __floats2half2_rn(shf[0], shf[1]);
        }
    }

    int re = g_rowptr[n0];
    for (int node = n0; node < n1; node++) {
        int rs = re;
        re = g_rowptr[node + 1];

        float acc[8];
#pragma unroll
        for (int j = 0; j < 8; j++) acc[j] = 0.f;

        for (int base = rs; base < re; base += 32) {
            int jj = base + lane;
            int sj = (jj < re) ? g_srcsorted[jj] : 0;
            int cnt = min(32, re - base);
            for (int u = 0; u < cnt; u += 4) {
                int i0 = u + q;
                int s = __shfl_sync(0xffffffffu, sj, i0 & 31);
                if (i0 < cnt) {
                    uint4 raw = *(const uint4*)(x_src + (size_t)s * D + c8 * 8);
                    __half2 v0 = u2h2(raw.x), v1 = u2h2(raw.y), v2 = u2h2(raw.z), v3 = u2h2(raw.w);
                    if (TF) {
                        __half2 z = __float2half2_rn(0.f);
                        v0 = __hmax2(__hfma2(v0, sc2[0], sh2[0]), z);
                        v1 = __hmax2(__hfma2(v1, sc2[1], sh2[1]), z);
                        v2 = __hmax2(__hfma2(v2, sc2[2], sh2[2]), z);
                        v3 = __hmax2(__hfma2(v3, sc2[3], sh2[3]), z);
                    }
                    float2 f0 = __half22float2(v0), f1 = __half22float2(v1);
                    float2 f2 = __half22float2(v2), f3 = __half22float2(v3);
                    acc[0] += f0.x; acc[1] += f0.y; acc[2] += f1.x; acc[3] += f1.y;
                    acc[4] += f2.x; acc[5] += f2.y; acc[6] += f3.x; acc[7] += f3.y;
                }
            }
        }

#pragma unroll
        for (int off = 8; off <= 16; off <<= 1)
#pragma unroll
            for (int j = 0; j < 8; j++) acc[j] += __shfl_xor_sync(0xffffffffu, acc[j], off);

        if (lane < 8) {
            float4* o = (float4*)(g_msg + (size_t)node * D + lane * 8);
            o[0] = make_float4(acc[0], acc[1], acc[2], acc[3]);
            o[1] = make_float4(acc[4], acc[5], acc[6], acc[7]);
        }
    }
}

// ---------------- helpers -----------------------------------------------------
__device__ __forceinline__ void bnrelu4(float4& a, const float4& sc, const float4& sh) {
    a.x = fmaxf(fmaf(a.x, sc.x, sh.x), 0.f);
    a.y = fmaxf(fmaf(a.y, sc.y, sh.y), 0.f);
    a.z = fmaxf(fmaf(a.z, sc.z, sh.z), 0.f);
    a.w = fmaxf(fmaf(a.w, sc.w, sh.w), 0.f);
}

// ---------------- gemm phase --------------------------------------------------
template<int TF>
__device__ void gemm_phase(float* smem,
                           const __half* __restrict__ x_src, __half* __restrict__ h_out,
                           const float* __restrict__ Wrel, const float* __restrict__ brel,
                           const float* __restrict__ Wroot,
                           const float* __restrict__ ssum_in, const float* __restrict__ ssq_in,
                           const float* __restrict__ gamma_p, const float* __restrict__ beta_p,
                           float* __restrict__ ssum_out, float* __restrict__ ssq_out,
                           float invN, int N)
{
    float* wa_sh = smem;
    float* wb_sh = smem + OFF_WB;
    float* m_sh  = smem + OFF_M;
    float* x_sh  = smem + OFF_X;
    float* s_br  = smem + OFF_BR;
    float* s_sc  = smem + OFF_SC;
    float* s_shf = smem + OFF_SH;
    float* s_sum = smem + OFF_SUM;
    float* s_sq  = smem + OFF_SQ;

    int tid = threadIdx.x;

    // stage weights once per layer
    for (int i = tid; i < 1024; i += NTHREADS) {
        int k = i >> 4, cq = i & 15;
        int dst = k * 17 + cq + (cq >= 8 ? 1 : 0);
        ((float4*)wa_sh)[dst] = ((const float4*)Wrel)[i];
        ((float4*)wb_sh)[dst] = ((const float4*)Wroot)[i];
    }
    if (tid < 64) {
        s_br[tid] = brel[tid];
        s_sum[tid] = 0.f;
        if (TF) {
            float mean = ssum_in[tid] * invN;
            float var = fmaf(-mean, mean, ssq_in[tid] * invN);
            var = var < 0.f ? 0.f : var;
            float s = gamma_p[tid] * rsqrtf(var + BN_EPS);
            s_sc[tid] = s;
            s_shf[tid] = beta_p[tid] - mean * s;
        }
    } else if (tid < 128) {
        s_sq[tid - 64] = 0.f;
    }
    __syncthreads();

    int lane = tid & 31;
    int cg = tid & 3;
    int p = tid >> 2;               // 0..63; rows p and p+64
    int c0 = cg * 16;
    int c0f = c0 + (cg >> 1) * 4;

    int ntiles = (N + TILE - 1) / TILE;
    for (int tile = blockIdx.x; tile < ntiles; tile += gridDim.x) {
        int tile0 = tile * TILE;

        // stage msg (fp32)
        for (int i = tid; i < TILE * 16; i += NTHREADS) {
            int r = i >> 4, c4 = i & 15;
            int node = tile0 + r;
            float4 mval = make_float4(0.f, 0.f, 0.f, 0.f);
            if (node < N) mval = ((const float4*)(g_msg + (size_t)node * D))[c4];
            ((float4*)(m_sh + r * AROW))[c4] = mval;
        }
        // stage x (fp16 -> fp32, BN+ReLU if TF)
        for (int i = tid; i < TILE * 8; i += NTHREADS) {
            int r = i >> 3, c8 = i & 7;
            int node = tile0 + r;
            float4 lo = make_float4(0.f, 0.f, 0.f, 0.f), hi = lo;
            if (node < N) {
                uint4 raw = ((const uint4*)(x_src + (size_t)node * D))[c8];
                float2 f0 = __half22float2(u2h2(raw.x));
                float2 f1 = __half22float2(u2h2(raw.y));
                float2 f2 = __half22float2(u2h2(raw.z));
                float2 f3 = __half22float2(u2h2(raw.w));
                lo = make_float4(f0.x, f0.y, f1.x, f1.y);
                hi = make_float4(f2.x, f2.y, f3.x, f3.y);
                if (TF) {
                    float4 sa = ((float4*)s_sc)[c8 * 2], ha = ((float4*)s_shf)[c8 * 2];
                    float4 sb = ((float4*)s_sc)[c8 * 2 + 1], hb = ((float4*)s_shf)[c8 * 2 + 1];
                    bnrelu4(lo, sa, ha);
                    bnrelu4(hi, sb, hb);
                }
            }
            *(float4*)(x_sh + r * AROW + c8 * 8) = lo;
            *(float4*)(x_sh + r * AROW + c8 * 8 + 4) = hi;
        }
        __syncthreads();

        ull acc0[8], acc1[8];
        {
            const ull* br2 = (const ull*)(s_br + c0);
#pragma unroll
            for (int qq = 0; qq < 8; qq++) { ull b = br2[qq]; acc0[qq] = b; acc1[qq] = b; }
        }

#pragma unroll 2
        for (int kk = 0; kk < 16; kk++) {
            float4 mq0 = *(const float4*)(m_sh + p * AROW + kk * 4);
            float4 mq1 = *(const float4*)(m_sh + (p + 64) * AROW + kk * 4);
            float4 xq0 = *(const float4*)(x_sh + p * AROW + kk * 4);
            float4 xq1 = *(const float4*)(x_sh + (p + 64) * AROW + kk * 4);
#pragma unroll
            for (int dk = 0; dk < 4; dk++) {
                int k = kk * 4 + dk;
                const ulonglong2* wa2 = (const ulonglong2*)(wa_sh + k * WROW + c0f);
                const ulonglong2* wb2 = (const ulonglong2*)(wb_sh + k * WROW + c0f);
                ulonglong2 A0 = wa2[0], A1 = wa2[1], A2 = wa2[2], A3 = wa2[3];
                ulonglong2 B0 = wb2[0], B1 = wb2[1], B2 = wb2[2], B3 = wb2[3];
                ull mm0, mm1, xx0, xx1;
                PK2(mm0, ((const float*)&mq0)[dk]);
                PK2(mm1, ((const float*)&mq1)[dk]);
                PK2(xx0, ((const float*)&xq0)[dk]);
                PK2(xx1, ((const float*)&xq1)[dk]);
                FMA2(acc0[0], mm0, A0.x, acc0[0]); FMA2(acc0[1], mm0, A0.y, acc0[1]);
                FMA2(acc0[2], mm0, A1.x, acc0[2]); FMA2(acc0[3], mm0, A1.y, acc0[3]);
                FMA2(acc0[4], mm0, A2.x, acc0[4]); FMA2(acc0[5], mm0, A2.y, acc0[5]);
                FMA2(acc0[6], mm0, A3.x, acc0[6]); FMA2(acc0[7], mm0, A3.y, acc0[7]);
                FMA2(acc1[0], mm1, A0.x, acc1[0]); FMA2(acc1[1], mm1, A0.y, acc1[1]);
                FMA2(acc1[2], mm1, A1.x, acc1[2]); FMA2(acc1[3], mm1, A1.y, acc1[3]);
                FMA2(acc1[4], mm1, A2.x, acc1[4]); FMA2(acc1[5], mm1, A2.y, acc1[5]);
                FMA2(acc1[6], mm1, A3.x, acc1[6]); FMA2(acc1[7], mm1, A3.y, acc1[7]);
                FMA2(acc0[0], xx0, B0.x, acc0[0]); FMA2(acc0[1], xx0, B0.y, acc0[1]);
                FMA2(acc0[2], xx0, B1.x, acc0[2]); FMA2(acc0[3], xx0, B1.y, acc0[3]);
                FMA2(acc0[4], xx0, B2.x, acc0[4]); FMA2(acc0[5], xx0, B2.y, acc0[5]);
                FMA2(acc0[6], xx0, B3.x, acc0[6]); FMA2(acc0[7], xx0, B3.y, acc0[7]);
                FMA2(acc1[0], xx1, B0.x, acc1[0]); FMA2(acc1[1], xx1, B0.y, acc1[1]);
                FMA2(acc1[2], xx1, B1.x, acc1[2]); FMA2(acc1[3], xx1, B1.y, acc1[3]);
                FMA2(acc1[4], xx1, B2.x, acc1[4]); FMA2(acc1[5], xx1, B2.y, acc1[5]);
                FMA2(acc1[6], xx1, B3.x, acc1[6]); FMA2(acc1[7], xx1, B3.y, acc1[7]);
            }
        }

        float s[16], q2[16];
#pragma unroll
        for (int qq = 0; qq < 16; qq++) { s[qq] = 0.f; q2[qq] = 0.f; }

#pragma unroll
        for (int j = 0; j < 2; j++) {
            int node = tile0 + p + 64 * j;
            bool valid = node < N;
            float h[16];
#pragma unroll
            for (int qq = 0; qq < 8; qq++) {
                ull a = j ? acc1[qq] : acc0[qq];
                UPK2(h[2 * qq], h[2 * qq + 1], a);
            }
            if (!valid) {
#pragma unroll
                for (int qq = 0; qq < 16; qq++) h[qq] = 0.f;
            }
#pragma unroll
            for (int qq = 0; qq < 16; qq++) { s[qq] += h[qq]; q2[qq] = fmaf(h[qq], h[qq], q2[qq]); }
            if (valid) {
                uint4 o0, o1;
                o0.x = h2u(__floats2half2_rn(h[0], h[1]));
                o0.y = h2u(__floats2half2_rn(h[2], h[3]));
                o0.z = h2u(__floats2half2_rn(h[4], h[5]));
                o0.w = h2u(__floats2half2_rn(h[6], h[7]));
                o1.x = h2u(__floats2half2_rn(h[8], h[9]));
                o1.y = h2u(__floats2half2_rn(h[10], h[11]));
                o1.z = h2u(__floats2half2_rn(h[12], h[13]));
                o1.w = h2u(__floats2half2_rn(h[14], h[15]));
                uint4* op = (uint4*)(h_out + (size_t)node * D + c0);
                op[0] = o0;
                op[1] = o1;
            }
        }

#pragma unroll
        for (int off = 4; off <= 16; off <<= 1) {
#pragma unroll
            for (int qq = 0; qq < 16; qq++) {
                s[qq]  += __shfl_xor_sync(0xffffffffu, s[qq], off);
                q2[qq] += __shfl_xor_sync(0xffffffffu, q2[qq], off);
            }
        }
        if (lane < 4) {
            int cc = lane * 16;
#pragma unroll
            for (int qq = 0; qq < 16; qq++) {
                atomicAdd(&s_sum[cc + qq], s[qq]);
                atomicAdd(&s_sq[cc + qq], q2[qq]);
            }
        }
        __syncthreads();   // before next tile restages m/x
    }

    // drain block-level stats once per layer
    if (tid < 64) atomicAdd(&ssum_out[tid], s_sum[tid]);
    else if (tid < 128) atomicAdd(&ssq_out[tid - 64], s_sq[tid - 64]);
}

// ---------------- megakernel --------------------------------------------------
extern "C" __global__ void __launch_bounds__(NTHREADS, 2) k_mega(
    const float* __restrict__ x, const int* __restrict__ ei, const int* __restrict__ batch,
    const float* __restrict__ Wrel, const float* __restrict__ brel,
    const float* __restrict__ Wroot,
    const float* __restrict__ gamma, const float* __restrict__ beta,
    const float* __restrict__ Wcls, const float* __restrict__ bcls,
    float* __restrict__ out,
    int N, int E, int G, int NB, float invN)
{
    extern __shared__ float smem[];
    int tid = threadIdx.x;
    int gtid = blockIdx.x * NTHREADS + tid;
    int gstride = gridDim.x * NTHREADS;

    // ---- P0: zero deg + stats, convert x -> fp16 ----
    for (int i = gtid; i < N; i += gstride) g_deg[i] = 0;
    for (int i = gtid; i < N * 8; i += gstride) {
        float4 a = ((const float4*)x)[i * 2];
        float4 b = ((const float4*)x)[i * 2 + 1];
        uint4 o;
        o.x = h2u(__floats2half2_rn(a.x, a.y));
        o.y = h2u(__floats2half2_rn(a.z, a.w));
        o.z = h2u(__floats2half2_rn(b.x, b.y));
        o.w = h2u(__floats2half2_rn(b.z, b.w));
        ((uint4*)g_xh)[i] = o;
    }
    if (blockIdx.x == 0 && tid < D) {
        g_s0[tid] = 0.f; g_q0[tid] = 0.f;
        g_s1[tid] = 0.f; g_q1[tid] = 0.f;
    }
    grid_bar();

    // ---- P1: histogram ----
    for (int e = gtid; e < E; e += gstride)
        atomicAdd(&g_deg[ei[E + e]], 1);
    grid_bar();

    // ---- P2: scan1 (per-chunk local scan) ----
    {
        int* ish = (int*)smem;
        for (int chunkb = blockIdx.x; chunkb < NB; chunkb += gridDim.x) {
            int base = chunkb * 1024 + tid * 4;
            int v0 = (base + 0 < N) ? g_deg[base + 0] : 0;
            int v1 = (base + 1 < N) ? g_deg[base + 1] : 0;
            int v2 = (base + 2 < N) ? g_deg[base + 2] : 0;
            int v3 = (base + 3 < N) ? g_deg[base + 3] : 0;
            int t0 = v0, t1 = t0 + v1, t2 = t1 + v2, t3 = t2 + v3;
            ish[tid] = t3;
            __syncthreads();
            for (int off = 1; off < 256; off <<= 1) {
                int a = (tid >= off) ? ish[tid - off] : 0;
                __syncthreads();
                ish[tid] += a;
                __syncthreads();
            }
            int excl = ish[tid] - t3;
            if (base + 0 < N) g_rowptr[base + 1] = excl + t0;
            if (base + 1 < N) g_rowptr[base + 2] = excl + t1;
            if (base + 2 < N) g_rowptr[base + 3] = excl + t2;
            if (base + 3 < N) g_rowptr[base + 4] = excl + t3;
            if (tid == 255) g_blocksums[chunkb] = ish[255];
            __syncthreads();
        }
    }
    grid_bar();

    // ---- P3: scan2+3 (each chunk re-scans blocksums, applies offset) ----
    {
        int* ish = (int*)smem;
        for (int chunkb = blockIdx.x; chunkb < NB; chunkb += gridDim.x) {
            int v = (tid < NB) ? g_blocksums[tid] : 0;
            ish[tid] = v;
            __syncthreads();
            for (int off = 1; off < 256; off <<= 1) {
                int a = (tid >= off) ? ish[tid - off] : 0;
                __syncthreads();
                ish[tid] += a;
                __syncthreads();
            }
            int off = (chunkb == 0) ? 0 : ish[chunkb - 1];
            int base = chunkb * 1024 + tid * 4;
#pragma unroll
            for (int i = 0; i < 4; i++) {
                int idx = base + i;
                if (idx < N) {
                    int val = g_rowptr[idx + 1] + off;
                    g_rowptr[idx + 1] = val;
                    if (idx + 1 < N) g_cursor[idx + 1] = val;
                }
            }
            if (chunkb == 0 && tid == 0) { g_rowptr[0] = 0; g_cursor[0] = 0; }
            __syncthreads();
        }
    }
    grid_bar();

    // ---- P4: bucket ----
    for (int e = gtid; e < E; e += gstride) {
        int dnode = ei[E + e];
        int pos = atomicAdd(&g_cursor[dnode], 1);
        g_srcsorted[pos] = ei[e];
    }
    grid_bar();

    // ---- layer 0 ----
    gather_phase<0>(g_xh, nullptr, nullptr, nullptr, nullptr, invN, N);
    grid_bar();
    gemm_phase<0>(smem, g_xh, g_hA, Wrel, brel, Wroot,
                  nullptr, nullptr, nullptr, nullptr, g_s0, g_q0, invN, N);
    grid_bar();

    // ---- layer 1 ----
    gather_phase<1>(g_hA, g_s0, g_q0, gamma, beta, invN, N);
    grid_bar();
    gemm_phase<1>(smem, g_hA, g_hB, Wrel + 4096, brel + 64, Wroot + 4096,
                  g_s0, g_q0, gamma, beta, g_s1, g_q1, invN, N);
    grid_bar();

    // ---- layer 2 (re-zero buf0 for its stats during the gather) ----
    if (blockIdx.x == 0 && tid < D) { g_s0[tid] = 0.f; g_q0[tid] = 0.f; }
    gather_phase<1>(g_hB, g_s1, g_q1, gamma + 64, beta + 64, invN, N);
    grid_bar();
    gemm_phase<1>(smem, g_hB, g_hA, Wrel + 8192, brel + 128, Wroot + 8192,
                  g_s1, g_q1, gamma + 64, beta + 64, g_s0, g_q0, invN, N);
    grid_bar();

    // ---- P11: pool + classifier (block g handles graph g) ----
    {
        float* s_pool = smem;
        int g = blockIdx.x;
        if (g < G) {
            int lo = 0, hi = N;
            while (lo < hi) { int mid = (lo + hi) >> 1; if (batch[mid] < g) lo = mid + 1; else hi = mid; }
            int start = lo;
            hi = N;
            while (lo < hi) { int mid = (lo + hi) >> 1; if (batch[mid] < g + 1) lo = mid + 1; else hi = mid; }
            int end = lo;

            if (tid < D) s_pool[tid] = 0.f;
            __syncthreads();

            int col = tid & 63, rg = tid >> 6;   // 4 row-groups
            float mean = g_s0[col] * invN;
            float var = fmaf(-mean, mean, g_q0[col] * invN);
            var = var < 0.f ? 0.f : var;
            float sc = gamma[128 + col] * rsqrtf(var + BN_EPS);
            float sh_ = beta[128 + col] - mean * sc;

            float p0 = 0.f, p1 = 0.f, p2 = 0.f, p3 = 0.f;
            float p4 = 0.f, p5 = 0.f, p6 = 0.f, p7 = 0.f;
            int r = start + rg;
            for (; r + 28 < end; r += 32) {
                p0 += fmaxf(fmaf(__half2float(g_hA[(size_t)(r     ) * D + col]), sc, sh_), 0.f);
                p1 += fmaxf(fmaf(__half2float(g_hA[(size_t)(r +  4) * D + col]), sc, sh_), 0.f);
                p2 += fmaxf(fmaf(__half2float(g_hA[(size_t)(r +  8) * D + col]), sc, sh_), 0.f);
                p3 += fmaxf(fmaf(__half2float(g_hA[(size_t)(r + 12) * D + col]), sc, sh_), 0.f);
                p4 += fmaxf(fmaf(__half2float(g_hA[(size_t)(r + 16) * D + col]), sc, sh_), 0.f);
                p5 += fmaxf(fmaf(__half2float(g_hA[(size_t)(r + 20) * D + col]), sc, sh_), 0.f);
                p6 += fmaxf(fmaf(__half2float(g_hA[(size_t)(r + 24) * D + col]), sc, sh_), 0.f);
                p7 += fmaxf(fmaf(__half2float(g_hA[(size_t)(r + 28) * D + col]), sc, sh_), 0.f);
            }
            for (; r < end; r += 4)
                p0 += fmaxf(fmaf(__half2float(g_hA[(size_t)r * D + col]), sc, sh_), 0.f);
            atomicAdd(&s_pool[col], ((p0 + p1) + (p2 + p3)) + ((p4 + p5) + (p6 + p7)));
            __syncthreads();

            float cnt = (float)(end - start);
            float denom = cnt > 1.f ? cnt : 1.f;
            if (tid < D) s_pool[tid] /= denom;
            __syncthreads();

            if (tid < 10) {
                float acc = bcls[tid];
#pragma unroll
                for (int d = 0; d < D; d++) acc = fmaf(s_pool[d], Wcls[d * 10 + tid], acc);
                out[g * 10 + tid] = acc;
            }
        }
    }
}

// ---------------- launch -----------------------------------------------------
extern "C" void kernel_launch(void* const* d_in, const int* in_sizes, int n_in,
                              void* d_out, int out_size)
{
    const float* x     = (const float*)d_in[0];
    const int*   ei    = (const int*)d_in[1];
    const int*   batch = (const int*)d_in[2];
    const float* Wrel  = (const float*)d_in[3];
    const float* brel  = (const float*)d_in[4];
    const float* Wroot = (const float*)d_in[5];
    const float* gamma = (const float*)d_in[6];
    const float* beta  = (const float*)d_in[7];
    const float* Wcls  = (const float*)d_in[8];
    const float* bcls  = (const float*)d_in[9];
    float* out = (float*)d_out;

    int N = in_sizes[0] / D;
    int E = in_sizes[1] / 2;
    int G = out_size / 10;
    int NB = (N + 1023) / 1024;
    float invN = 1.f / (float)N;
    size_t smemb = SMEM_FLOATS * sizeof(float);

    static int nblk = 0;
    if (!nblk) {
        cudaFuncSetAttribute(k_mega, cudaFuncAttributeMaxDynamicSharedMemorySize, (int)smemb);
        int dev = 0, nsm = 148, occ = 1;
        cudaGetDevice(&dev);
        cudaDeviceGetAttribute(&nsm, cudaDevAttrMultiProcessorCount, dev);
        cudaOccupancyMaxActiveBlocksPerMultiprocessor(&occ, k_mega, NTHREADS, smemb);
        if (occ < 1) occ = 1;
        if (occ > 2) occ = 2;
        nblk = nsm * occ;
    }

    k_mega<<<nblk, NTHREADS, smemb>>>(x, ei, batch, Wrel, brel, Wroot,
                                      gamma, beta, Wcls, bcls, out,
                                      N, E, G, NB, invN);
}

// round 10
// speedup vs baseline: 2.0177x; 2.0177x over previous
#include <cuda_runtime.h>
#include <cuda_fp16.h>

#define D 64
#define MAXN 100000
#define MAXE 1250000
#define BN_EPS 1e-5f
#define TILE 128
#define AROWH 136
#define WROWH 72

__device__ __forceinline__ __half2 u2h2(unsigned u) { return *reinterpret_cast<__half2*>(&u); }
__device__ __forceinline__ unsigned h2u(__half2 h) { return *reinterpret_cast<unsigned*>(&h); }

// ---------------- static device scratch -------------------------------------
__device__ int   g_deg[MAXN];
__device__ int   g_rowptr[MAXN + 1];
__device__ int   g_cursor[MAXN + 1];
__device__ int   g_blocksums[256];
__device__ int   g_srcsorted[MAXE];
__device__ __align__(16) __half g_xh[(size_t)MAXN * D];
__device__ __align__(16) __half g_msg[(size_t)MAXN * D];
__device__ __align__(16) __half g_hA[(size_t)MAXN * D];
__device__ __align__(16) __half g_hB[(size_t)MAXN * D];
__device__ __align__(16) float g_s0[D];
__device__ __align__(16) float g_q0[D];
__device__ __align__(16) float g_s1[D];
__device__ __align__(16) float g_q1[D];

// ---------------- CSR build + fp16 convert -----------------------------------
__global__ void k_setup(const float* __restrict__ x, int N, int total8) {
    int i = blockIdx.x * blockDim.x + threadIdx.x;
    if (i < N) g_deg[i] = 0;
    if (i < total8) {
        float4 a = ((const float4*)x)[i * 2];
        float4 b = ((const float4*)x)[i * 2 + 1];
        uint4 o;
        o.x = h2u(__floats2half2_rn(a.x, a.y));
        o.y = h2u(__floats2half2_rn(a.z, a.w));
        o.z = h2u(__floats2half2_rn(b.x, b.y));
        o.w = h2u(__floats2half2_rn(b.z, b.w));
        ((uint4*)g_xh)[i] = o;
    }
    if (blockIdx.x == 0 && threadIdx.x < D) {
        g_s0[threadIdx.x] = 0.f; g_q0[threadIdx.x] = 0.f;
        g_s1[threadIdx.x] = 0.f; g_q1[threadIdx.x] = 0.f;
    }
}

__global__ void k_hist(const int* __restrict__ ei, int E) {
    int e = blockIdx.x * blockDim.x + threadIdx.x;
    if (e < E) atomicAdd(&g_deg[ei[E + e]], 1);
}

__global__ void k_scan1(int N) {
    __shared__ int sh[256];
    int tid = threadIdx.x;
    int base = blockIdx.x * 1024 + tid * 4;
    int v0 = (base + 0 < N) ? g_deg[base + 0] : 0;
    int v1 = (base + 1 < N) ? g_deg[base + 1] : 0;
    int v2 = (base + 2 < N) ? g_deg[base + 2] : 0;
    int v3 = (base + 3 < N) ? g_deg[base + 3] : 0;
    int t0 = v0, t1 = t0 + v1, t2 = t1 + v2, t3 = t2 + v3;
    sh[tid] = t3;
    __syncthreads();
    for (int off = 1; off < 256; off <<= 1) {
        int add = (tid >= off) ? sh[tid - off] : 0;
        __syncthreads();
        sh[tid] += add;
        __syncthreads();
    }
    int excl = sh[tid] - t3;
    if (base + 0 < N) g_rowptr[base + 1] = excl + t0;
    if (base + 1 < N) g_rowptr[base + 2] = excl + t1;
    if (base + 2 < N) g_rowptr[base + 3] = excl + t2;
    if (base + 3 < N) g_rowptr[base + 4] = excl + t3;
    if (tid == 255) g_blocksums[blockIdx.x] = sh[255];
}

__global__ void k_scan23(int N, int NB) {
    __shared__ int sh[256];
    int tid = threadIdx.x;
    int v = (tid < NB) ? g_blocksums[tid] : 0;
    sh[tid] = v;
    __syncthreads();
    for (int off = 1; off < 256; off <<= 1) {
        int a = (tid >= off) ? sh[tid - off] : 0;
        __syncthreads();
        sh[tid] += a;
        __syncthreads();
    }
    int off = (blockIdx.x == 0) ? 0 : sh[blockIdx.x - 1];

    int base = blockIdx.x * 1024 + tid * 4;
#pragma unroll
    for (int i = 0; i < 4; i++) {
        int idx = base + i;
        if (idx < N) {
            int val = g_rowptr[idx + 1] + off;
            g_rowptr[idx + 1] = val;
            if (idx + 1 < N) g_cursor[idx + 1] = val;
        }
    }
    if (blockIdx.x == 0 && tid == 0) { g_rowptr[0] = 0; g_cursor[0] = 0; }
}

__global__ void k_bucket(const int* __restrict__ ei, int E) {
    int e = blockIdx.x * blockDim.x + threadIdx.x;
    if (e < E) {
        int d = ei[E + e];
        int pos = atomicAdd(&g_cursor[d], 1);
        g_srcsorted[pos] = ei[e];
    }
}

// ---------------- gather: warp per node, fp16 in/out --------------------------
template<int TF>
__global__ void __launch_bounds__(256) k_gather(
    const __half* __restrict__ x_src,
    const float* __restrict__ ssum, const float* __restrict__ ssq,
    const float* __restrict__ gamma_p, const float* __restrict__ beta_p,
    float* zsum, float* zsq, float invN, int N)
{
    if (TF && zsum != nullptr && blockIdx.x == 0 && threadIdx.x < D) {
        zsum[threadIdx.x] = 0.f;
        zsq[threadIdx.x]  = 0.f;
    }

    int lane = threadIdx.x & 31;
    int node = (blockIdx.x * blockDim.x + threadIdx.x) >> 5;
    if (node >= N) return;
    int q = lane >> 3;
    int c8 = lane & 7;

    __half2 sc2[4], sh2[4];
    if (TF) {
#pragma unroll
        for (int j = 0; j < 4; j++) {
            float scf[2], shf[2];
#pragma unroll
            for (int c = 0; c < 2; c++) {
                int col = c8 * 8 + j * 2 + c;
                float mean = ssum[col] * invN;
                float var = fmaf(-mean, mean, ssq[col] * invN);
                var = var < 0.f ? 0.f : var;
                float s = gamma_p[col] * rsqrtf(var + BN_EPS);
                scf[c] = s;
                shf[c] = beta_p[col] - mean * s;
            }
            sc2[j] = __floats2half2_rn(scf[0], scf[1]);
            sh2[j] = __floats2half2_rn(shf[0], shf[1]);
        }
    }

    float acc[8];
#pragma unroll
    for (int j = 0; j < 8; j++) acc[j] = 0.f;

    int rs = g_rowptr[node], re = g_rowptr[node + 1];
    for (int base = rs; base < re; base += 32) {
        int jj = base + lane;
        int sj = (jj < re) ? g_srcsorted[jj] : 0;
        int cnt = min(32, re - base);
        for (int u = 0; u < cnt; u += 4) {
            int i0 = u + q;
            int s = __shfl_sync(0xffffffffu, sj, i0 & 31);
            if (i0 < cnt) {
                uint4 raw = *(const uint4*)(x_src + (size_t)s * D + c8 * 8);
                __half2 v0 = u2h2(raw.x), v1 = u2h2(raw.y), v2 = u2h2(raw.z), v3 = u2h2(raw.w);
                if (TF) {
                    __half2 z = __float2half2_rn(0.f);
                    v0 = __hmax2(__hfma2(v0, sc2[0], sh2[0]), z);
                    v1 = __hmax2(__hfma2(v1, sc2[1], sh2[1]), z);
                    v2 = __hmax2(__hfma2(v2, sc2[2], sh2[2]), z);
                    v3 = __hmax2(__hfma2(v3, sc2[3], sh2[3]), z);
                }
                float2 f0 = __half22float2(v0), f1 = __half22float2(v1);
                float2 f2 = __half22float2(v2), f3 = __half22float2(v3);
                acc[0] += f0.x; acc[1] += f0.y; acc[2] += f1.x; acc[3] += f1.y;
                acc[4] += f2.x; acc[5] += f2.y; acc[6] += f3.x; acc[7] += f3.y;
            }
        }
    }

#pragma unroll
    for (int off = 8; off <= 16; off <<= 1)
#pragma unroll
        for (int j = 0; j < 8; j++) acc[j] += __shfl_xor_sync(0xffffffffu, acc[j], off);

    if (lane < 8) {
        uint4 o;
        o.x = h2u(__floats2half2_rn(acc[0], acc[1]));
        o.y = h2u(__floats2half2_rn(acc[2], acc[3]));
        o.z = h2u(__floats2half2_rn(acc[4], acc[5]));
        o.w = h2u(__floats2half2_rn(acc[6], acc[7]));
        *(uint4*)(g_msg + (size_t)node * D + lane * 8) = o;
    }
}

// ---------------- tensor-core GEMM: [msg|x](Nx128) @ [Wrel;Wroot](128x64) -----
#define SMEM_A_BYTES (128 * AROWH * 2)
#define SMEM_W_OFF   SMEM_A_BYTES
#define SMEM_F_OFF   (SMEM_A_BYTES + 128 * WROWH * 2)
#define SMEM_BYTES   (SMEM_F_OFF + 64 * 4 * 3 + 64 * 2 * 2)

template<int TF>
__global__ void __launch_bounds__(256) k_gemm(
    const __half* __restrict__ x_src, __half* __restrict__ h_out,
    const float* __restrict__ Wrel, const float* __restrict__ brel,
    const float* __restrict__ Wroot,
    const float* __restrict__ ssum_in, const float* __restrict__ ssq_in,
    const float* __restrict__ gamma_p, const float* __restrict__ beta_p,
    float* __restrict__ ssum_out, float* __restrict__ ssq_out,
    float invN, int N)
{
    extern __shared__ char smemc[];
    __half* a_sh = (__half*)smemc;
    __half* w_sh = (__half*)(smemc + SMEM_W_OFF);
    float* s_bias = (float*)(smemc + SMEM_F_OFF);
    float* s_sum = s_bias + 64;
    float* s_sq  = s_sum + 64;
    __half* s_sch = (__half*)(s_sq + 64);
    __half* s_shh = s_sch + 64;

    int tid = threadIdx.x;
    int lane = tid & 31;
    int w = tid >> 5;

    // stage W (fp32 -> fp16) once per block
    for (int i = tid; i < 1024; i += 256) {
        int k = i >> 4, n4 = (i & 15) * 4;
        float4 v = ((const float4*)Wrel)[i];
        uint2 hv;
        hv.x = h2u(__floats2half2_rn(v.x, v.y));
        hv.y = h2u(__floats2half2_rn(v.z, v.w));
        *(uint2*)(w_sh + k * WROWH + n4) = hv;
        float4 u = ((const float4*)Wroot)[i];
        uint2 hu;
        hu.x = h2u(__floats2half2_rn(u.x, u.y));
        hu.y = h2u(__floats2half2_rn(u.z, u.w));
        *(uint2*)(w_sh + (64 + k) * WROWH + n4) = hu;
    }
    if (tid < 64) {
        s_bias[tid] = brel[tid];
        s_sum[tid] = 0.f;
        s_sq[tid] = 0.f;
        if (TF) {
            float mean = ssum_in[tid] * invN;
            float var = fmaf(-mean, mean, ssq_in[tid] * invN);
            var = var < 0.f ? 0.f : var;
            float s = gamma_p[tid] * rsqrtf(var + BN_EPS);
            s_sch[tid] = __float2half_rn(s);
            s_shh[tid] = __float2half_rn(beta_p[tid] - mean * s);
        }
    }

    unsigned sbase = (unsigned)__cvta_generic_to_shared(smemc);
    unsigned a_addr = sbase + ((16 * w + (lane & 15)) * AROWH + ((lane >> 4) << 3)) * 2;
    unsigned b_addr = sbase + SMEM_W_OFF + ((lane & 15) * WROWH + ((lane >> 4) << 3)) * 2;

    int grp = lane >> 2, tig = lane & 3;
    float sl[16], ql[16];
#pragma unroll
    for (int i = 0; i < 16; i++) { sl[i] = 0.f; ql[i] = 0.f; }

    int ntiles = (N + TILE - 1) / TILE;
    for (int tile = blockIdx.x; tile < ntiles; tile += gridDim.x) {
        int tile0 = tile * TILE;
        __syncthreads();

        // stage A = [msg | x] rows (fp16): 128 rows x 16 uint4 (128 halves/row)
        for (int i = tid; i < 2048; i += 256) {
            int r = i >> 4, seg = i & 15;
            int node = tile0 + r;
            uint4 val = make_uint4(0u, 0u, 0u, 0u);
            if (node < N) {
                if (seg < 8) {
                    val = ((const uint4*)(g_msg + (size_t)node * D))[seg];
                } else {
                    val = ((const uint4*)(x_src + (size_t)node * D))[seg - 8];
                    if (TF) {
                        int cb2 = (seg - 8) * 4;
                        const __half2* scp = (const __half2*)s_sch;
                        const __half2* shp = (const __half2*)s_shh;
                        __half2 z = __float2half2_rn(0.f);
                        val.x = h2u(__hmax2(__hfma2(u2h2(val.x), scp[cb2 + 0], shp[cb2 + 0]), z));
                        val.y = h2u(__hmax2(__hfma2(u2h2(val.y), scp[cb2 + 1], shp[cb2 + 1]), z));
                        val.z = h2u(__hmax2(__hfma2(u2h2(val.z), scp[cb2 + 2], shp[cb2 + 2]), z));
                        val.w = h2u(__hmax2(__hfma2(u2h2(val.w), scp[cb2 + 3], shp[cb2 + 3]), z));
                    }
                }
            }
            *(uint4*)(a_sh + r * AROWH + seg * 8) = val;
        }
        __syncthreads();

        // accumulators (init with bias)
        float c[8][4];
#pragma unroll
        for (int nt = 0; nt < 8; nt++) {
            float b0 = s_bias[nt * 8 + tig * 2];
            float b1 = s_bias[nt * 8 + tig * 2 + 1];
            c[nt][0] = b0; c[nt][1] = b1; c[nt][2] = b0; c[nt][3] = b1;
        }

#pragma unroll
        for (int ks = 0; ks < 8; ks++) {
            unsigned a0, a1, a2, a3;
            asm volatile("ldmatrix.sync.aligned.m8n8.x4.shared.b16 {%0,%1,%2,%3}, [%4];"
                         : "=r"(a0), "=r"(a1), "=r"(a2), "=r"(a3)
                         : "r"(a_addr + ks * 32));
#pragma unroll
            for (int nt4 = 0; nt4 < 4; nt4++) {
                unsigned b0, b1, b2, b3;
                asm volatile("ldmatrix.sync.aligned.m8n8.x4.trans.shared.b16 {%0,%1,%2,%3}, [%4];"
                             : "=r"(b0), "=r"(b1), "=r"(b2), "=r"(b3)
                             : "r"(b_addr + ks * (16 * WROWH * 2) + nt4 * 32));
                asm volatile("mma.sync.aligned.m16n8k16.row.col.f32.f16.f16.f32 "
                             "{%0,%1,%2,%3}, {%4,%5,%6,%7}, {%8,%9}, {%0,%1,%2,%3};"
                             : "+f"(c[2 * nt4][0]), "+f"(c[2 * nt4][1]), "+f"(c[2 * nt4][2]), "+f"(c[2 * nt4][3])
                             : "r"(a0), "r"(a1), "r"(a2), "r"(a3), "r"(b0), "r"(b1));
                asm volatile("mma.sync.aligned.m16n8k16.row.col.f32.f16.f16.f32 "
                             "{%0,%1,%2,%3}, {%4,%5,%6,%7}, {%8,%9}, {%0,%1,%2,%3};"
                             : "+f"(c[2 * nt4 + 1][0]), "+f"(c[2 * nt4 + 1][1]), "+f"(c[2 * nt4 + 1][2]), "+f"(c[2 * nt4 + 1][3])
                             : "r"(a0), "r"(a1), "r"(a2), "r"(a3), "r"(b2), "r"(b3));
            }
        }

        // epilogue: store h (fp16) + accumulate BN stats
        int row0 = tile0 + 16 * w + grp;
        int row1 = row0 + 8;
        bool v0 = row0 < N, v1 = row1 < N;
#pragma unroll
        for (int nt = 0; nt < 8; nt++) {
            int col = nt * 8 + tig * 2;
            if (v0) {
                *(unsigned*)(h_out + (size_t)row0 * D + col) = h2u(__floats2half2_rn(c[nt][0], c[nt][1]));
                sl[2 * nt]     += c[nt][0];
                ql[2 * nt]      = fmaf(c[nt][0], c[nt][0], ql[2 * nt]);
                sl[2 * nt + 1] += c[nt][1];
                ql[2 * nt + 1]  = fmaf(c[nt][1], c[nt][1], ql[2 * nt + 1]);
            }
            if (v1) {
                *(unsigned*)(h_out + (size_t)row1 * D + col) = h2u(__floats2half2_rn(c[nt][2], c[nt][3]));
                sl[2 * nt]     += c[nt][2];
                ql[2 * nt]      = fmaf(c[nt][2], c[nt][2], ql[2 * nt]);
                sl[2 * nt + 1] += c[nt][3];
                ql[2 * nt + 1]  = fmaf(c[nt][3], c[nt][3], ql[2 * nt + 1]);
            }
        }
    }

    // reduce stats over row-groups (lanes differing in bits 2..4 share tig)
#pragma unroll
    for (int off = 4; off <= 16; off <<= 1) {
#pragma unroll
        for (int i = 0; i < 16; i++) {
            sl[i] += __shfl_xor_sync(0xffffffffu, sl[i], off);
            ql[i] += __shfl_xor_sync(0xffffffffu, ql[i], off);
        }
    }
    if (lane < 4) {
#pragma unroll
        for (int nt = 0; nt < 8; nt++) {
            atomicAdd(&s_sum[nt * 8 + 2 * lane],     sl[2 * nt]);
            atomicAdd(&s_sum[nt * 8 + 2 * lane + 1], sl[2 * nt + 1]);
            atomicAdd(&s_sq[nt * 8 + 2 * lane],      ql[2 * nt]);
            atomicAdd(&s_sq[nt * 8 + 2 * lane + 1],  ql[2 * nt + 1]);
        }
    }
    __syncthreads();
    if (tid < 64) atomicAdd(&ssum_out[tid], s_sum[tid]);
    else if (tid < 128) atomicAdd(&ssq_out[tid - 64], s_sq[tid - 64]);
}

// ---------------- pooling + classifier (final BN+ReLU inline) ----------------
__global__ void __launch_bounds__(1024) k_pool(
    const __half* __restrict__ hfin, const int* __restrict__ batch, int N,
    const float* __restrict__ Wcls, const float* __restrict__ bcls,
    const float* __restrict__ ssum, const float* __restrict__ ssq,
    const float* __restrict__ gamma_p, const float* __restrict__ beta_p,
    float invN, float* __restrict__ out)
{
    __shared__ float s_pool[D];
    int g = blockIdx.x, tid = threadIdx.x;

    int lo = 0, hi = N;
    while (lo < hi) { int mid = (lo + hi) >> 1; if (batch[mid] < g) lo = mid + 1; else hi = mid; }
    int start = lo;
    hi = N;
    while (lo < hi) { int mid = (lo + hi) >> 1; if (batch[mid] < g + 1) lo = mid + 1; else hi = mid; }
    int end = lo;

    if (tid < D) s_pool[tid] = 0.f;
    __syncthreads();

    int col = tid & 63, rg = tid >> 6;
    float mean = ssum[col] * invN;
    float var = fmaf(-mean, mean, ssq[col] * invN);
    var = var < 0.f ? 0.f : var;
    float sc = gamma_p[col] * rsqrtf(var + BN_EPS);
    float sh_ = beta_p[col] - mean * sc;

    float p0 = 0.f, p1 = 0.f, p2 = 0.f, p3 = 0.f;
    int r = start + rg;
    for (; r + 48 < end; r += 64) {
        float a0 = __half2float(hfin[(size_t)(r     ) * D + col]);
        float a1 = __half2float(hfin[(size_t)(r + 16) * D + col]);
        float a2 = __half2float(hfin[(size_t)(r + 32) * D + col]);
        float a3 = __half2float(hfin[(size_t)(r + 48) * D + col]);
        p0 += fmaxf(fmaf(a0, sc, sh_), 0.f);
        p1 += fmaxf(fmaf(a1, sc, sh_), 0.f);
        p2 += fmaxf(fmaf(a2, sc, sh_), 0.f);
        p3 += fmaxf(fmaf(a3, sc, sh_), 0.f);
    }
    for (; r < end; r += 16)
        p0 += fmaxf(fmaf(__half2float(hfin[(size_t)r * D + col]), sc, sh_), 0.f);
    atomicAdd(&s_pool[col], ((p0 + p1) + (p2 + p3)));
    __syncthreads();

    float cnt = (float)(end - start);
    float denom = cnt > 1.f ? cnt : 1.f;
    if (tid < D) s_pool[tid] /= denom;
    __syncthreads();

    if (tid < 10) {
        float acc = bcls[tid];
#pragma unroll
        for (int d = 0; d < D; d++) acc = fmaf(s_pool[d], Wcls[d * 10 + tid], acc);
        out[g * 10 + tid] = acc;
    }
}

// ---------------- launch -----------------------------------------------------
extern "C" void kernel_launch(void* const* d_in, const int* in_sizes, int n_in,
                              void* d_out, int out_size)
{
    const float* x     = (const float*)d_in[0];
    const int*   ei    = (const int*)d_in[1];
    const int*   batch = (const int*)d_in[2];
    const float* Wrel  = (const float*)d_in[3];
    const float* brel  = (const float*)d_in[4];
    const float* Wroot = (const float*)d_in[5];
    const float* gamma = (const float*)d_in[6];
    const float* beta  = (const float*)d_in[7];
    const float* Wcls  = (const float*)d_in[8];
    const float* bcls  = (const float*)d_in[9];
    float* out = (float*)d_out;

    int N = in_sizes[0] / D;
    int E = in_sizes[1] / 2;
    int G = out_size / 10;
    int NB = (N + 1023) / 1024;
    float invN = 1.f / (float)N;
    int NTILES = (N + TILE - 1) / TILE;
    int GATHER_BLOCKS = (N * 32 + 255) / 256;
    int total8 = N * 8;
    int GEMM_BLOCKS = NTILES < 296 ? NTILES : 296;

    static int attr_done = 0;
    if (!attr_done) {
        cudaFuncSetAttribute(k_gemm<0>, cudaFuncAttributeMaxDynamicSharedMemorySize, SMEM_BYTES);
        cudaFuncSetAttribute(k_gemm<1>, cudaFuncAttributeMaxDynamicSharedMemorySize, SMEM_BYTES);
        attr_done = 1;
    }

    __half *xh, *hA, *hB;
    float *s0, *q0, *s1, *q1;
    cudaGetSymbolAddress((void**)&xh, g_xh);
    cudaGetSymbolAddress((void**)&hA, g_hA);
    cudaGetSymbolAddress((void**)&hB, g_hB);
    cudaGetSymbolAddress((void**)&s0, g_s0);
    cudaGetSymbolAddress((void**)&q0, g_q0);
    cudaGetSymbolAddress((void**)&s1, g_s1);
    cudaGetSymbolAddress((void**)&q1, g_q1);

    // CSR build + fp16 convert
    k_setup<<<(total8 + 255) / 256, 256>>>(x, N, total8);
    k_hist<<<(E + 255) / 256, 256>>>(ei, E);
    k_scan1<<<NB, 256>>>(N);
    k_scan23<<<NB, 256>>>(N, NB);
    k_bucket<<<(E + 255) / 256, 256>>>(ei, E);

    // layer 0: xh -> hA (stats -> buf0)
    k_gather<0><<<GATHER_BLOCKS, 256>>>(xh, nullptr, nullptr, nullptr, nullptr,
                                        nullptr, nullptr, invN, N);
    k_gemm<0><<<GEMM_BLOCKS, 256, SMEM_BYTES>>>(xh, hA, Wrel, brel, Wroot,
                                                nullptr, nullptr, nullptr, nullptr,
                                                s0, q0, invN, N);

    // layer 1: hA -> hB (BN from buf0; stats -> buf1)
    k_gather<1><<<GATHER_BLOCKS, 256>>>(hA, s0, q0, gamma, beta,
                                        nullptr, nullptr, invN, N);
    k_gemm<1><<<GEMM_BLOCKS, 256, SMEM_BYTES>>>(hA, hB, Wrel + 4096, brel + 64, Wroot + 4096,
                                                s0, q0, gamma, beta,
                                                s1, q1, invN, N);

    // layer 2: hB -> hA (BN from buf1; stats -> buf0, zeroed by gather2 block 0)
    k_gather<1><<<GATHER_BLOCKS, 256>>>(hB, s1, q1, gamma + 64, beta + 64,
                                        s0, q0, invN, N);
    k_gemm<1><<<GEMM_BLOCKS, 256, SMEM_BYTES>>>(hB, hA, Wrel + 8192, brel + 128, Wroot + 8192,
                                                s1, q1, gamma + 64, beta + 64,
                                                s0, q0, invN, N);

    // pool (applies layer-2 BN+ReLU from buf0 stats) + classifier
    k_pool<<<G, 1024>>>(hA, batch, N, Wcls, bcls,
                        s0, q0, gamma + 128, beta + 128, invN, out);
}